// round 6
// baseline (speedup 1.0000x reference)
#include <cuda_runtime.h>
#include <math.h>

#define N_TOK 8192
#define DIM   4096
#define NEXP  16
#define TPB   256
#define TOK   32                      /* tokens per block */
#define KHALF 2048                    /* k per half (2-way k-split in block) */
#define CH_ROWS 256                   /* gate rows per chunk per half */
#define NCHUNK (KHALF / CH_ROWS)      /* 8 */
#define NG     (KHALF / 16)           /* 128 16-k groups per lane sweep */

#define GBUF_HALF_BYTES  (CH_ROWS * 64)          /* 16384 */
#define GBUF_STAGE_BYTES (2 * GBUF_HALF_BYTES)   /* 32768 */
#define GBUF_BYTES       (2 * GBUF_STAGE_BYTES)  /* 65536 */
#define PART_BYTES       (2 * TOK * NEXP * 4)    /* 4096  */
#define SM_BYTES         (GBUF_BYTES + PART_BYTES + 128)

#define FMA2(acc, a, b) \
    asm("fma.rn.f32x2 %0, %1, %2, %0;" : "+l"(acc) : "l"(a), "l"(b))

/* gate smem slot swizzle: row r, expert-quad m -> byte offset.
   Makes the 4 rows {q*4+j} (q=0..3) of one k-substep hit disjoint
   16B bank regions -> conflict-free broadcast LDS.128. */
__device__ __forceinline__ int gswz(int row, int m) {
    return row * 64 + (((m + (row >> 2)) & 3) << 4);
}

__global__ void __launch_bounds__(TPB, 2)
router_kernel(const float* __restrict__ x,
              const float* __restrict__ gate,
              float* __restrict__ out, int out_size)
{
    extern __shared__ char smc[];
    char*  gbuf = smc;                       // gate chunks [stage][half][row][64B]
    float* part = (float*)(smc + GBUF_BYTES); // [2][TOK][16]

    const int tid = threadIdx.x;
    const int w = tid >> 5, l = tid & 31;
    const int h  = w >> 2;                   // k half 0/1
    const int tw = w & 3;                    // token octet
    const int tok = blockIdx.x * TOK + tw * 8 + (l & 7);
    const int q = l >> 3;                    // k-quad interleave 0..3

    // lane's x base: token row, half offset, quad offset (16B aligned)
    const float* xp = x + (size_t)tok * DIM + h * KHALF + q * 4;

    // staging roles (all 256 threads)
    const int s_half = tid >> 7;
    const int s_m    = tid & 3;
    const int s_row0 = (tid >> 2) & 31;

    unsigned long long acc[8];
#pragma unroll
    for (int i = 0; i < 8; i++) acc[i] = 0ull;

    // ---- prologue: stage gate chunk 0 (both halves) into stage 0 ----
    {
        const float4* gsrc = (const float4*)gate;
#pragma unroll
        for (int it = 0; it < 8; it++) {
            int row = s_row0 + it * 32;
            float4 v = gsrc[(size_t)(s_half * KHALF + row) * 4 + s_m];
            *(float4*)(gbuf + s_half * GBUF_HALF_BYTES + gswz(row, s_m)) = v;
        }
    }
    __syncthreads();

    // x prefetch pair (g, g+1)
    float4 xa = *(const float4*)(xp);
    float4 xb = *(const float4*)(xp + 16);

    for (int c = 0; c < NCHUNK; c++) {
        // per-m base pointers: swizzle + q folded in -> inner LDS uses immediates
        const char* gb = gbuf + (c & 1) * GBUF_STAGE_BYTES
                              + h * GBUF_HALF_BYTES + q * 256;
        const char* pm0 = gb + (((0 + q) & 3) << 4);
        const char* pm1 = gb + (((1 + q) & 3) << 4);
        const char* pm2 = gb + (((2 + q) & 3) << 4);
        const char* pm3 = gb + (((3 + q) & 3) << 4);

        // issue staging loads for chunk c+1 (land during compute)
        float4 sreg[8];
        if (c + 1 < NCHUNK) {
            const float4* gsrc = (const float4*)
                (gate + (size_t)(s_half * KHALF + (c + 1) * CH_ROWS) * NEXP);
#pragma unroll
            for (int it = 0; it < 8; it++)
                sreg[it] = gsrc[(size_t)(s_row0 + it * 32) * 4 + s_m];
        }

#define COMPUTE_G(G, V)                                                        \
        {                                                                      \
            _Pragma("unroll")                                                  \
            for (int j = 0; j < 4; j++) {                                      \
                float xj = ((const float*)&(V))[j];                            \
                unsigned long long xd_;                                        \
                asm("mov.b64 %0, {%1,%1};" : "=l"(xd_) : "f"(xj));             \
                const int ro = ((G) * 16 + j) * 64;                            \
                ulonglong2 G0 = *(const ulonglong2*)(pm0 + ro);                \
                ulonglong2 G1 = *(const ulonglong2*)(pm1 + ro);                \
                ulonglong2 G2 = *(const ulonglong2*)(pm2 + ro);                \
                ulonglong2 G3 = *(const ulonglong2*)(pm3 + ro);                \
                FMA2(acc[0], xd_, G0.x); FMA2(acc[1], xd_, G0.y);              \
                FMA2(acc[2], xd_, G1.x); FMA2(acc[3], xd_, G1.y);              \
                FMA2(acc[4], xd_, G2.x); FMA2(acc[5], xd_, G2.y);              \
                FMA2(acc[6], xd_, G3.x); FMA2(acc[7], xd_, G3.y);              \
            }                                                                  \
        }

#pragma unroll
        for (int g2 = 0; g2 < 16; g2 += 2) {
            const int gg = c * 16 + g2;
            int gp0 = gg + 2 < NG ? gg + 2 : NG - 1;   // clamp (no OOB)
            int gp1 = gg + 3 < NG ? gg + 3 : NG - 1;
            float4 xc = *(const float4*)(xp + gp0 * 16);
            float4 xd = *(const float4*)(xp + gp1 * 16);
            COMPUTE_G(g2,     xa);
            COMPUTE_G(g2 + 1, xb);
            xa = xc; xb = xd;
        }
#undef COMPUTE_G

        // write staged gate regs into the other buffer
        if (c + 1 < NCHUNK) {
#pragma unroll
            for (int it = 0; it < 8; it++) {
                int row = s_row0 + it * 32;
                *(float4*)(gbuf + ((c + 1) & 1) * GBUF_STAGE_BYTES
                                + s_half * GBUF_HALF_BYTES
                                + gswz(row, s_m)) = sreg[it];
            }
        }
        __syncthreads();
    }

    // ---- butterfly-reduce the 4-way q split within the warp ----
#pragma unroll
    for (int i = 0; i < 8; i++) {
        float2 v = *(float2*)&acc[i];
        v.x += __shfl_xor_sync(0xffffffffu, v.x, 8);
        v.y += __shfl_xor_sync(0xffffffffu, v.y, 8);
        v.x += __shfl_xor_sync(0xffffffffu, v.x, 16);
        v.y += __shfl_xor_sync(0xffffffffu, v.y, 16);
        *(float2*)&acc[i] = v;
    }

    // lanes q==0 write per-half partials: part[h][tokLocal][16]
    if (q == 0) {
        float* p = part + (size_t)(h * TOK + tw * 8 + (l & 7)) * NEXP;
#pragma unroll
        for (int i = 0; i < 8; i++)
            *(float2*)(p + 2 * i) = *(float2*)&acc[i];
    }
    __syncthreads();

    // combine the two k-halves: thread -> (token, expert pair)
    {
        int t = tid >> 3, e2 = (tid & 7) * 2;
        float2 a = *(const float2*)(part + (size_t)t * NEXP + e2);
        float2 b = *(const float2*)(part + (size_t)(TOK + t) * NEXP + e2);
        a.x += b.x; a.y += b.y;
        __syncthreads();
        *(float2*)(part + (size_t)t * NEXP + e2) = a;
    }
    __syncthreads();

    // ---- top-2 + sigmoid + transposed score writes ----
    if (tid < TOK) {
        int t = tid;
        float v[NEXP];
#pragma unroll
        for (int e = 0; e < NEXP; e++) v[e] = part[t * NEXP + e];
        float v1 = -INFINITY, v2 = -INFINITY;
        int   i1 = -1,        i2 = -1;
#pragma unroll
        for (int e = 0; e < NEXP; e++) {
            float tv = v[e];
            if (tv > v1)      { v2 = v1; i2 = i1; v1 = tv; i1 = e; }
            else if (tv > v2) { v2 = tv; i2 = e; }
        }
        int gtok = blockIdx.x * TOK + t;
#pragma unroll
        for (int e = 0; e < NEXP; e++) {
            float sc = (e == i1 || e == i2) ? (1.0f / (1.0f + expf(-v[e]))) : 0.0f;
            out[(size_t)e * N_TOK + gtok] = sc;   // 32 consecutive tokens: coalesced
        }
    }

    // ---- token_indices (second output region), values as floats ----
    if (out_size >= 2 * NEXP * N_TOK) {
        int e  = tid >> 4;            // 0..15
        int c2 = (tid & 15) * 2;      // token pair within block
        int gtok = blockIdx.x * TOK + c2;
        float2 fv = make_float2((float)gtok, (float)(gtok + 1));
        *(float2*)(out + (size_t)NEXP * N_TOK + (size_t)e * N_TOK + gtok) = fv;
    }
}

extern "C" void kernel_launch(void* const* d_in, const int* in_sizes, int n_in,
                              void* d_out, int out_size)
{
    const float* x    = (const float*)d_in[0];
    const float* gate = (const float*)d_in[1];
    float* out = (float*)d_out;

    cudaFuncSetAttribute(router_kernel,
                         cudaFuncAttributeMaxDynamicSharedMemorySize, SM_BYTES);

    dim3 grid(N_TOK / TOK);   // 256 blocks, 2 CTAs/SM
    dim3 block(TPB);
    router_kernel<<<grid, block, SM_BYTES>>>(x, gate, out, out_size);
}

// round 7
// speedup vs baseline: 1.5796x; 1.5796x over previous
#include <cuda_runtime.h>
#include <math.h>

#define N_TOK 8192
#define DIM   4096
#define NEXP  16
#define TPB   256
#define NWARP 8
#define TOK   32
#define KSL   (DIM / NWARP)       /* 512 k per warp */
#define KT    32                  /* k per tile */
#define NT    (KSL / KT)          /* 16 tiles */
#define XSTR  33                  /* x smem row stride (words) — conflict-free */

#define W_XS  (KT * XSTR)         /* 1056 f */
#define W_GS  (KT * NEXP)         /*  512 f */
#define W_FL  (W_XS + W_GS)
#define SM_FLOATS (NWARP * W_FL + NWARP * TOK * NEXP + TOK * NEXP)
#define SM_BYTES  (SM_FLOATS * 4) /* 68608 B -> 2 CTAs/SM */

#define FMA2(acc, a, b) \
    asm("fma.rn.f32x2 %0, %1, %2, %0;" : "+l"(acc) : "l"(a), "l"(b))

__global__ void __launch_bounds__(TPB, 2)
router_kernel(const float* __restrict__ x, const float* __restrict__ gate,
              float* __restrict__ out, int out_size)
{
    extern __shared__ float sm[];
    float* part = sm + NWARP * W_FL;           // [NWARP][TOK][16]
    float* lg   = part + NWARP * TOK * NEXP;   // [TOK][16]

    const int tid = threadIdx.x;
    const int w = tid >> 5, l = tid & 31;
    const int tokBase = blockIdx.x * TOK;
    const int kw = w * KSL;

    float* xs = sm + w * W_FL;    // [KT][XSTR]  x transposed, stride 33
    float* gs = xs + W_XS;        // [KT][16]    gate rows, plain

    // staging roles
    const int tokr = l >> 3;      // 0..3
    const int kq8  = l & 7;       // 0..7 (k quad within tile)
    // compute roles: lane = kq*8 + tg*2 + eg
    const int kq = l >> 3;        // 0..3 k-interleave
    const int tg = (l >> 1) & 3;  // token octet: tokens 8tg..8tg+7
    const int eg = l & 1;         // expert half: experts 8eg..8eg+7

    // acc[i*4+ep]: token 8tg+i, expert pair {8eg+2ep, 8eg+2ep+1}
    unsigned long long acc[32];
#pragma unroll
    for (int i = 0; i < 32; i++) acc[i] = 0ull;

    // x prefetch: 8 rounds, (token 4rd+tokr, k quad kq8) — nL=4 coalescing
    float4 xr[8];
#pragma unroll
    for (int rd = 0; rd < 8; rd++)
        xr[rd] = *(const float4*)(x + (size_t)(tokBase + 4 * rd + tokr) * DIM
                                  + kw + 4 * kq8);

#pragma unroll 1
    for (int t = 0; t < NT; t++) {
        __syncwarp();   // previous tile's smem reads complete

        // ---- STS x tile (STS.32, conflict-free: banks = 4kq8+j+4rd+tokr) ----
#pragma unroll
        for (int rd = 0; rd < 8; rd++) {
            float* col = xs + (4 * rd + tokr);
            col[(4 * kq8 + 0) * XSTR] = xr[rd].x;
            col[(4 * kq8 + 1) * XSTR] = xr[rd].y;
            col[(4 * kq8 + 2) * XSTR] = xr[rd].z;
            col[(4 * kq8 + 3) * XSTR] = xr[rd].w;
        }
        // ---- stage gate tile (L2-hot, contiguous) ----
        {
            const float4* gsrc = (const float4*)(gate + (size_t)(kw + t * KT) * NEXP);
#pragma unroll
            for (int rd = 0; rd < 4; rd++)
                ((float4*)gs)[rd * 32 + l] = gsrc[rd * 32 + l];
        }
        __syncwarp();

        // ---- prefetch x tile t+1 (lands during compute) ----
        if (t + 1 < NT) {
#pragma unroll
            for (int rd = 0; rd < 8; rd++)
                xr[rd] = *(const float4*)(x + (size_t)(tokBase + 4 * rd + tokr) * DIM
                                          + kw + (t + 1) * KT + 4 * kq8);
        }

        // ---- compute: 8 batches, lane's k = 4b + kq ----
#pragma unroll
        for (int b = 0; b < 8; b++) {
            const int k = 4 * b + kq;
            const ulonglong2* gp = (const ulonglong2*)(gs + k * NEXP + 8 * eg);
            ulonglong2 Ga = gp[0], Gb = gp[1];     // 4 natural expert pairs
            const float* xrow = xs + k * XSTR + 8 * tg;
#pragma unroll
            for (int i = 0; i < 8; i++) {
                float xv = xrow[i];                 // LDS.32, conflict-free
                unsigned long long xd;
                asm("mov.b64 %0, {%1,%1};" : "=l"(xd) : "f"(xv));
                FMA2(acc[i * 4 + 0], xd, Ga.x);
                FMA2(acc[i * 4 + 1], xd, Ga.y);
                FMA2(acc[i * 4 + 2], xd, Gb.x);
                FMA2(acc[i * 4 + 3], xd, Gb.y);
            }
        }
    }

    // ---- butterfly-reduce the 4-way k-interleave (lanes xor 8, 16) ----
#pragma unroll
    for (int i = 0; i < 32; i++) {
        float2 v = *(float2*)&acc[i];
        v.x += __shfl_xor_sync(0xffffffffu, v.x, 8);
        v.y += __shfl_xor_sync(0xffffffffu, v.y, 8);
        v.x += __shfl_xor_sync(0xffffffffu, v.x, 16);
        v.y += __shfl_xor_sync(0xffffffffu, v.y, 16);
        *(float2*)&acc[i] = v;
    }
    // lanes kq==0 hold the warp partial for (tg, eg)
    if (kq == 0) {
#pragma unroll
        for (int i = 0; i < 8; i++) {
            float* dst = part + (size_t)(w * TOK + 8 * tg + i) * NEXP + 8 * eg;
#pragma unroll
            for (int ep = 0; ep < 4; ep++)
                *(float2*)(dst + 2 * ep) = *(float2*)&acc[i * 4 + ep];
        }
    }
    __syncthreads();

    // ---- deterministic 8-warp tree reduce: thread -> (token, expert pair) ----
    {
        int tok = tid >> 3, e2 = (tid & 7) * 2;
        float2 s = make_float2(0.f, 0.f);
#pragma unroll
        for (int ww = 0; ww < NWARP; ww++) {
            float2 v = *(const float2*)(part + (size_t)(ww * TOK + tok) * NEXP + e2);
            s.x += v.x; s.y += v.y;
        }
        *(float2*)(lg + tok * NEXP + e2) = s;
    }
    __syncthreads();

    // ---- top-2 + sigmoid + transposed score writes ----
    if (tid < TOK) {
        int t = tid;
        float v[NEXP];
#pragma unroll
        for (int e = 0; e < NEXP; e++) v[e] = lg[t * NEXP + e];
        float v1 = -INFINITY, v2 = -INFINITY;
        int   i1 = -1,        i2 = -1;
#pragma unroll
        for (int e = 0; e < NEXP; e++) {
            float tv = v[e];
            if (tv > v1)      { v2 = v1; i2 = i1; v1 = tv; i1 = e; }
            else if (tv > v2) { v2 = tv; i2 = e; }
        }
        int gtok = tokBase + t;
#pragma unroll
        for (int e = 0; e < NEXP; e++) {
            float sc = (e == i1 || e == i2) ? (1.0f / (1.0f + expf(-v[e]))) : 0.0f;
            out[(size_t)e * N_TOK + gtok] = sc;   // 32 consecutive tokens: coalesced
        }
    }

    // ---- token_indices (second output region), values as floats ----
    if (out_size >= 2 * NEXP * N_TOK) {
        int e  = tid >> 4;            // 0..15
        int c2 = (tid & 15) * 2;      // token pair within block
        int gtok = tokBase + c2;
        float2 fv = make_float2((float)gtok, (float)(gtok + 1));
        *(float2*)(out + (size_t)NEXP * N_TOK + (size_t)e * N_TOK + gtok) = fv;
    }
}

extern "C" void kernel_launch(void* const* d_in, const int* in_sizes, int n_in,
                              void* d_out, int out_size)
{
    const float* x    = (const float*)d_in[0];
    const float* gate = (const float*)d_in[1];
    float* out = (float*)d_out;

    cudaFuncSetAttribute(router_kernel,
                         cudaFuncAttributeMaxDynamicSharedMemorySize, SM_BYTES);

    dim3 grid(N_TOK / TOK);   // 256 blocks, 2 CTAs/SM
    dim3 block(TPB);
    router_kernel<<<grid, block, SM_BYTES>>>(x, gate, out, out_size);
}